// round 6
// baseline (speedup 1.0000x reference)
#include <cuda_runtime.h>
#include <cuda_bf16.h>

// Problem constants (fixed by the dataset)
#define N_NODES 100000
#define F_DIM   64
#define E_MAX   1600000

// Scratch (device globals only — no cudaMalloc allowed).
__device__ __align__(16) float g_sum[2][N_NODES * F_DIM];   // mean features
__device__ int g_cnti[2][N_NODES];        // histogram
__device__ int g_off [2][N_NODES + 1];    // CSR offsets
__device__ int g_cur [2][N_NODES];        // fill cursors
__device__ int g_srcs[2][E_MAX];          // dst-sorted src ids

// ---------------------------------------------------------------------------
// 1) zero histogram counters (graph replays -> every call).
// ---------------------------------------------------------------------------
__global__ void zero_cnt_kernel() {
    unsigned i = blockIdx.x * blockDim.x + threadIdx.x;
    if (i < 2u * N_NODES) ((int*)g_cnti)[i] = 0;
}

// ---------------------------------------------------------------------------
// 2) histogram of dst per edge set.
// ---------------------------------------------------------------------------
__global__ void hist_kernel(const int* __restrict__ pos_ei,
                            const int* __restrict__ neg_ei, int E) {
    unsigned i = blockIdx.x * blockDim.x + threadIdx.x;
    if (i >= 2u * (unsigned)E) return;
    int set = (i >= (unsigned)E);
    unsigned e = set ? i - (unsigned)E : i;
    const int* ei = set ? neg_ei : pos_ei;
    int dst = ei[(unsigned)E + e];
    atomicAdd(&g_cnti[set][dst], 1);
}

// ---------------------------------------------------------------------------
// 3) exclusive prefix scan of the histogram -> offsets + cursors.
//    One 1024-thread block per edge set.
// ---------------------------------------------------------------------------
__global__ void scan_kernel() {
    const int set = blockIdx.x;
    const int tid = threadIdx.x;
    const int CH  = (N_NODES + 1023) / 1024;   // 98
    __shared__ int part[1024];

    int beg = tid * CH;
    int end = min(beg + CH, N_NODES);
    int s = 0;
    for (int i = beg; i < end; i++) s += g_cnti[set][i];
    part[tid] = s;
    __syncthreads();
    // Hillis-Steele inclusive scan
    for (int d = 1; d < 1024; d <<= 1) {
        int v = (tid >= d) ? part[tid - d] : 0;
        __syncthreads();
        part[tid] += v;
        __syncthreads();
    }
    if (tid == 1023) g_off[set][N_NODES] = part[1023];
    int run = (tid == 0) ? 0 : part[tid - 1];
    for (int i = beg; i < end; i++) {
        int c = g_cnti[set][i];
        g_off[set][i] = run;
        g_cur[set][i] = run;
        run += c;
    }
}

// ---------------------------------------------------------------------------
// 4) fill: counting-sort edges by dst (src ids into CSR slots).
// ---------------------------------------------------------------------------
__global__ void fill_kernel(const int* __restrict__ pos_ei,
                            const int* __restrict__ neg_ei, int E) {
    unsigned i = blockIdx.x * blockDim.x + threadIdx.x;
    if (i >= 2u * (unsigned)E) return;
    int set = (i >= (unsigned)E);
    unsigned e = set ? i - (unsigned)E : i;
    const int* ei = set ? neg_ei : pos_ei;
    int src = ei[e];
    int dst = ei[(unsigned)E + e];
    int pos = atomicAdd(&g_cur[set][dst], 1);
    g_srcs[set][pos] = src;
}

// ---------------------------------------------------------------------------
// 5) gather: per (set, node, float4-chunk) thread, register-accumulate the
//    node's neighborhood and store the MEAN. No atomics.
//    16 consecutive threads share a node -> each edge is a coalesced 256B read.
// ---------------------------------------------------------------------------
__global__ void gather_kernel(const float* __restrict__ x) {
    unsigned idx = blockIdx.x * blockDim.x + threadIdx.x;
    const unsigned per_set = (unsigned)N_NODES * 16u;
    if (idx >= 2u * per_set) return;
    int set = (idx >= per_set);
    unsigned r = set ? idx - per_set : idx;
    unsigned n = r >> 4;
    unsigned c = r & 15u;

    int beg = g_off[set][n];
    int end = g_off[set][n + 1];
    const int* __restrict__ srcs = g_srcs[set];

    float4 acc = make_float4(0.f, 0.f, 0.f, 0.f);
    int e = beg;
    for (; e + 2 <= end; e += 2) {
        int s0 = __ldg(&srcs[e]);
        int s1 = __ldg(&srcs[e + 1]);
        float4 v0 = __ldg((const float4*)(x + (unsigned)s0 * 64u) + c);
        float4 v1 = __ldg((const float4*)(x + (unsigned)s1 * 64u) + c);
        acc.x += v0.x + v1.x; acc.y += v0.y + v1.y;
        acc.z += v0.z + v1.z; acc.w += v0.w + v1.w;
    }
    if (e < end) {
        int s0 = __ldg(&srcs[e]);
        float4 v0 = __ldg((const float4*)(x + (unsigned)s0 * 64u) + c);
        acc.x += v0.x; acc.y += v0.y; acc.z += v0.z; acc.w += v0.w;
    }
    float inv = 1.f / (float)max(end - beg, 1);
    acc.x *= inv; acc.y *= inv; acc.z *= inv; acc.w *= inv;
    ((float4*)(g_sum[set] + n * 64u))[c] = acc;
}

// ---------------------------------------------------------------------------
// 6) fused SGEMM + epilogue (pure fp32 FMA). g_sum now holds means.
// ---------------------------------------------------------------------------
__global__ __launch_bounds__(256) void gemm_kernel(
        const float* __restrict__ x,
        const float* __restrict__ Wp,
        const float* __restrict__ Wpc,
        const float* __restrict__ bp,
        const float* __restrict__ Wn,
        const float* __restrict__ Wnc,
        const float* __restrict__ bn,
        float* __restrict__ out) {
    __shared__ float xs[16][132];   // x tile (k-major)
    __shared__ float sp[16][132];   // mean_pos tile
    __shared__ float sn[16][132];   // mean_neg tile
    __shared__ float Wa[16][128];   // aggregate weight
    __shared__ float Wc[16][128];   // self(cc) weight

    const int tid = threadIdx.x;
    const int tc  = tid & 15;
    const int tr  = tid >> 4;
    const int row0 = blockIdx.x * 128;
    const int c0   = tc * 8;
    const bool pos_side = (tc < 8);

    float acc[8][8];
    #pragma unroll
    for (int r = 0; r < 8; r++)
        #pragma unroll
        for (int c = 0; c < 8; c++) acc[r][c] = 0.f;

    for (int k0 = 0; k0 < 64; k0 += 16) {
        __syncthreads();
        #pragma unroll
        for (int t = 0; t < 2; t++) {
            int i     = tid * 2 + t;
            int chunk = i & 3;
            int row   = i >> 2;
            int grow  = row0 + row;
            float4 vx = make_float4(0.f,0.f,0.f,0.f);
            float4 vp = vx, vn = vx;
            if (grow < N_NODES) {
                vx = *((const float4*)(x        + grow * 64 + k0) + chunk);
                vp = *((const float4*)(g_sum[0] + grow * 64 + k0) + chunk);
                vn = *((const float4*)(g_sum[1] + grow * 64 + k0) + chunk);
            }
            int kb = chunk * 4;
            xs[kb+0][row] = vx.x; xs[kb+1][row] = vx.y;
            xs[kb+2][row] = vx.z; xs[kb+3][row] = vx.w;
            sp[kb+0][row] = vp.x; sp[kb+1][row] = vp.y;
            sp[kb+2][row] = vp.z; sp[kb+3][row] = vp.w;
            sn[kb+0][row] = vn.x; sn[kb+1][row] = vn.y;
            sn[kb+2][row] = vn.z; sn[kb+3][row] = vn.w;
        }
        #pragma unroll
        for (int t = 0; t < 8; t++) {
            int i = t * 256 + tid;
            int j = i & 127;
            int k = i >> 7;
            int jj = j & 63;
            const float* W1 = (j < 64) ? Wp  : Wn;
            const float* W2 = (j < 64) ? Wpc : Wnc;
            Wa[k][j] = W1[jj * 64 + k0 + k];
            Wc[k][j] = W2[jj * 64 + k0 + k];
        }
        __syncthreads();

        const float (*at)[132] = pos_side ? sp : sn;
        #pragma unroll
        for (int k = 0; k < 16; k++) {
            float a[8], xv[8], w1[8], w2[8];
            #pragma unroll
            for (int r = 0; r < 8; r++) {
                a[r]  = at[k][tr * 8 + r];
                xv[r] = xs[k][tr * 8 + r];
            }
            #pragma unroll
            for (int c = 0; c < 8; c++) {
                w1[c] = Wa[k][c0 + c];
                w2[c] = Wc[k][c0 + c];
            }
            #pragma unroll
            for (int r = 0; r < 8; r++)
                #pragma unroll
                for (int c = 0; c < 8; c++)
                    acc[r][c] += a[r] * w1[c] + xv[r] * w2[c];
        }
    }

    float b[8];
    #pragma unroll
    for (int c = 0; c < 8; c++) {
        int j = c0 + c;
        b[c] = pos_side ? bp[j] : bn[j - 64];
    }
    #pragma unroll
    for (int r = 0; r < 8; r++) {
        int grow = row0 + tr * 8 + r;
        if (grow < N_NODES) {
            #pragma unroll
            for (int c = 0; c < 8; c++)
                out[grow * 128 + c0 + c] = acc[r][c] + b[c];
        }
    }
}

// ---------------------------------------------------------------------------
extern "C" void kernel_launch(void* const* d_in, const int* in_sizes, int n_in,
                              void* d_out, int out_size) {
    const float* x   = (const float*)d_in[0];
    const int*   pe  = (const int*)d_in[1];   // int32 (JAX downcasts int64)
    const int*   ne  = (const int*)d_in[2];
    const float* Wp  = (const float*)d_in[3];
    const float* Wpc = (const float*)d_in[4];
    const float* bp  = (const float*)d_in[5];
    const float* Wn  = (const float*)d_in[6];
    const float* Wnc = (const float*)d_in[7];
    const float* bn  = (const float*)d_in[8];
    float* out = (float*)d_out;

    int E = in_sizes[1] / 2;   // edge_index is [2, E]

    zero_cnt_kernel<<<(2 * N_NODES + 255) / 256, 256>>>();
    hist_kernel<<<(2 * E + 255) / 256, 256>>>(pe, ne, E);
    scan_kernel<<<2, 1024>>>();
    fill_kernel<<<(2 * E + 255) / 256, 256>>>(pe, ne, E);
    gather_kernel<<<(2 * N_NODES * 16 + 255) / 256, 256>>>(x);
    gemm_kernel<<<(N_NODES + 127) / 128, 256>>>(x, Wp, Wpc, bp, Wn, Wnc, bn, out);
}

// round 7
// speedup vs baseline: 1.4176x; 1.4176x over previous
#include <cuda_runtime.h>
#include <cuda_bf16.h>

// Problem constants (fixed by the dataset)
#define N_NODES 100000
#define F_DIM   64
#define E_MAX   1600000
#define TOT_CNT (2 * N_NODES)            // 200000 flat counters (pos then neg)
#define SCAN_BLOCKS ((TOT_CNT + 1023) / 1024)   // 196

// Scratch (device globals only — no cudaMalloc allowed).
__device__ __align__(16) float g_sum[2][N_NODES * F_DIM];  // mean features
__device__ __align__(16) int g_cnt [TOT_CNT];       // flat histogram
__device__ __align__(16) int g_off [TOT_CNT + 1];   // flat CSR offsets
__device__ __align__(16) int g_cur [TOT_CNT];       // fill cursors
__device__ int g_part [SCAN_BLOCKS];                // per-block partial sums
__device__ int g_bloff[SCAN_BLOCKS];                // per-block exclusive offset
__device__ int g_srcs [2 * E_MAX];                  // dst-sorted src ids (flat)

// ---------------------------------------------------------------------------
// 1) zero histogram counters.
// ---------------------------------------------------------------------------
__global__ void zero_cnt_kernel() {
    unsigned i = blockIdx.x * blockDim.x + threadIdx.x;
    if (i < TOT_CNT) g_cnt[i] = 0;
}

// ---------------------------------------------------------------------------
// 2) histogram of dst (flat: set1 counters live at N_NODES + dst).
// ---------------------------------------------------------------------------
__global__ void hist_kernel(const int* __restrict__ pos_ei,
                            const int* __restrict__ neg_ei, int E) {
    unsigned i = blockIdx.x * blockDim.x + threadIdx.x;
    if (i >= 2u * (unsigned)E) return;
    int set = (i >= (unsigned)E);
    unsigned e = set ? i - (unsigned)E : i;
    const int* ei = set ? neg_ei : pos_ei;
    int dst = ei[(unsigned)E + e];
    atomicAdd(&g_cnt[set * N_NODES + dst], 1);
}

// ---------------------------------------------------------------------------
// 3a) per-block partial sums (1024 counters per block, coalesced int4).
// ---------------------------------------------------------------------------
__global__ void scanA_kernel() {
    const int b = blockIdx.x, t = threadIdx.x;
    int base = b * 1024 + t * 4;
    int4 v = make_int4(0, 0, 0, 0);
    if (base + 3 < TOT_CNT)      v = *(const int4*)&g_cnt[base];
    else if (base < TOT_CNT) {
        v.x = g_cnt[base];
        if (base + 1 < TOT_CNT) v.y = g_cnt[base + 1];
        if (base + 2 < TOT_CNT) v.z = g_cnt[base + 2];
    }
    int s = v.x + v.y + v.z + v.w;
    // warp reduce
    for (int d = 16; d > 0; d >>= 1) s += __shfl_down_sync(0xffffffffu, s, d);
    __shared__ int ws[8];
    if ((t & 31) == 0) ws[t >> 5] = s;
    __syncthreads();
    if (t == 0) {
        int tot = 0;
        #pragma unroll
        for (int w = 0; w < 8; w++) tot += ws[w];
        g_part[b] = tot;
    }
}

// ---------------------------------------------------------------------------
// 3b) scan of the block partials (single small block).
// ---------------------------------------------------------------------------
__global__ void scanB_kernel() {
    const int t = threadIdx.x;
    __shared__ int sm[256];
    int v = (t < SCAN_BLOCKS) ? g_part[t] : 0;
    sm[t] = v;
    __syncthreads();
    for (int d = 1; d < 256; d <<= 1) {
        int u = (t >= d) ? sm[t - d] : 0;
        __syncthreads();
        sm[t] += u;
        __syncthreads();
    }
    if (t < SCAN_BLOCKS) g_bloff[t] = sm[t] - v;     // exclusive
    if (t == 255) g_off[TOT_CNT] = sm[255];          // grand total
}

// ---------------------------------------------------------------------------
// 3c) write flat exclusive offsets + cursors (coalesced).
// ---------------------------------------------------------------------------
__global__ void scanC_kernel() {
    const int b = blockIdx.x, t = threadIdx.x;
    int base = b * 1024 + t * 4;
    int4 v = make_int4(0, 0, 0, 0);
    if (base + 3 < TOT_CNT)      v = *(const int4*)&g_cnt[base];
    else if (base < TOT_CNT) {
        v.x = g_cnt[base];
        if (base + 1 < TOT_CNT) v.y = g_cnt[base + 1];
        if (base + 2 < TOT_CNT) v.z = g_cnt[base + 2];
    }
    int ts = v.x + v.y + v.z + v.w;
    // block exclusive scan of ts
    __shared__ int sm[256];
    sm[t] = ts;
    __syncthreads();
    for (int d = 1; d < 256; d <<= 1) {
        int u = (t >= d) ? sm[t - d] : 0;
        __syncthreads();
        sm[t] += u;
        __syncthreads();
    }
    int o = g_bloff[b] + sm[t] - ts;   // exclusive prefix for this thread
    if (base < TOT_CNT) {
        int o0 = o, o1 = o0 + v.x, o2 = o1 + v.y, o3 = o2 + v.z;
        g_off[base] = o0; g_cur[base] = o0;
        if (base + 1 < TOT_CNT) { g_off[base + 1] = o1; g_cur[base + 1] = o1; }
        if (base + 2 < TOT_CNT) { g_off[base + 2] = o2; g_cur[base + 2] = o2; }
        if (base + 3 < TOT_CNT) { g_off[base + 3] = o3; g_cur[base + 3] = o3; }
    }
}

// ---------------------------------------------------------------------------
// 4) fill: counting-sort edges by dst (src ids into flat CSR slots).
// ---------------------------------------------------------------------------
__global__ void fill_kernel(const int* __restrict__ pos_ei,
                            const int* __restrict__ neg_ei, int E) {
    unsigned i = blockIdx.x * blockDim.x + threadIdx.x;
    if (i >= 2u * (unsigned)E) return;
    int set = (i >= (unsigned)E);
    unsigned e = set ? i - (unsigned)E : i;
    const int* ei = set ? neg_ei : pos_ei;
    int src = ei[e];
    int dst = ei[(unsigned)E + e];
    int pos = atomicAdd(&g_cur[set * N_NODES + dst], 1);
    g_srcs[pos] = src;
}

// ---------------------------------------------------------------------------
// 5) gather: per (set,node,chunk) thread, 4-way unrolled register
//    accumulation of the neighborhood; store the MEAN. No atomics.
// ---------------------------------------------------------------------------
__global__ void gather_kernel(const float* __restrict__ x) {
    unsigned idx = blockIdx.x * blockDim.x + threadIdx.x;
    const unsigned per_set = (unsigned)N_NODES * 16u;
    if (idx >= 2u * per_set) return;
    int set = (idx >= per_set);
    unsigned r = set ? idx - per_set : idx;
    unsigned n = r >> 4;
    unsigned c = r & 15u;
    unsigned gid = (unsigned)set * N_NODES + n;

    int beg = g_off[gid];
    int end = g_off[gid + 1];

    float4 a0 = make_float4(0.f,0.f,0.f,0.f), a1 = a0, a2 = a0, a3 = a0;
    int e = beg;
    for (; e + 4 <= end; e += 4) {
        int s0 = __ldg(&g_srcs[e]);
        int s1 = __ldg(&g_srcs[e + 1]);
        int s2 = __ldg(&g_srcs[e + 2]);
        int s3 = __ldg(&g_srcs[e + 3]);
        float4 v0 = __ldg((const float4*)(x + (unsigned)s0 * 64u) + c);
        float4 v1 = __ldg((const float4*)(x + (unsigned)s1 * 64u) + c);
        float4 v2 = __ldg((const float4*)(x + (unsigned)s2 * 64u) + c);
        float4 v3 = __ldg((const float4*)(x + (unsigned)s3 * 64u) + c);
        a0.x += v0.x; a0.y += v0.y; a0.z += v0.z; a0.w += v0.w;
        a1.x += v1.x; a1.y += v1.y; a1.z += v1.z; a1.w += v1.w;
        a2.x += v2.x; a2.y += v2.y; a2.z += v2.z; a2.w += v2.w;
        a3.x += v3.x; a3.y += v3.y; a3.z += v3.z; a3.w += v3.w;
    }
    for (; e < end; e++) {
        int s0 = __ldg(&g_srcs[e]);
        float4 v0 = __ldg((const float4*)(x + (unsigned)s0 * 64u) + c);
        a0.x += v0.x; a0.y += v0.y; a0.z += v0.z; a0.w += v0.w;
    }
    float4 acc;
    acc.x = (a0.x + a1.x) + (a2.x + a3.x);
    acc.y = (a0.y + a1.y) + (a2.y + a3.y);
    acc.z = (a0.z + a1.z) + (a2.z + a3.z);
    acc.w = (a0.w + a1.w) + (a2.w + a3.w);
    float inv = 1.f / (float)max(end - beg, 1);
    acc.x *= inv; acc.y *= inv; acc.z *= inv; acc.w *= inv;
    ((float4*)(g_sum[set] + n * 64u))[c] = acc;
}

// ---------------------------------------------------------------------------
// 6) fused SGEMM + epilogue (pure fp32 FMA). g_sum holds means.
// ---------------------------------------------------------------------------
__global__ __launch_bounds__(256) void gemm_kernel(
        const float* __restrict__ x,
        const float* __restrict__ Wp,
        const float* __restrict__ Wpc,
        const float* __restrict__ bp,
        const float* __restrict__ Wn,
        const float* __restrict__ Wnc,
        const float* __restrict__ bn,
        float* __restrict__ out) {
    __shared__ float xs[16][132];
    __shared__ float sp[16][132];
    __shared__ float sn[16][132];
    __shared__ float Wa[16][128];
    __shared__ float Wc[16][128];

    const int tid = threadIdx.x;
    const int tc  = tid & 15;
    const int tr  = tid >> 4;
    const int row0 = blockIdx.x * 128;
    const int c0   = tc * 8;
    const bool pos_side = (tc < 8);

    float acc[8][8];
    #pragma unroll
    for (int r = 0; r < 8; r++)
        #pragma unroll
        for (int c = 0; c < 8; c++) acc[r][c] = 0.f;

    for (int k0 = 0; k0 < 64; k0 += 16) {
        __syncthreads();
        #pragma unroll
        for (int t = 0; t < 2; t++) {
            int i     = tid * 2 + t;
            int chunk = i & 3;
            int row   = i >> 2;
            int grow  = row0 + row;
            float4 vx = make_float4(0.f,0.f,0.f,0.f);
            float4 vp = vx, vn = vx;
            if (grow < N_NODES) {
                vx = *((const float4*)(x        + grow * 64 + k0) + chunk);
                vp = *((const float4*)(g_sum[0] + grow * 64 + k0) + chunk);
                vn = *((const float4*)(g_sum[1] + grow * 64 + k0) + chunk);
            }
            int kb = chunk * 4;
            xs[kb+0][row] = vx.x; xs[kb+1][row] = vx.y;
            xs[kb+2][row] = vx.z; xs[kb+3][row] = vx.w;
            sp[kb+0][row] = vp.x; sp[kb+1][row] = vp.y;
            sp[kb+2][row] = vp.z; sp[kb+3][row] = vp.w;
            sn[kb+0][row] = vn.x; sn[kb+1][row] = vn.y;
            sn[kb+2][row] = vn.z; sn[kb+3][row] = vn.w;
        }
        #pragma unroll
        for (int t = 0; t < 8; t++) {
            int i = t * 256 + tid;
            int j = i & 127;
            int k = i >> 7;
            int jj = j & 63;
            const float* W1 = (j < 64) ? Wp  : Wn;
            const float* W2 = (j < 64) ? Wpc : Wnc;
            Wa[k][j] = W1[jj * 64 + k0 + k];
            Wc[k][j] = W2[jj * 64 + k0 + k];
        }
        __syncthreads();

        const float (*at)[132] = pos_side ? sp : sn;
        #pragma unroll
        for (int k = 0; k < 16; k++) {
            float a[8], xv[8], w1[8], w2[8];
            #pragma unroll
            for (int r = 0; r < 8; r++) {
                a[r]  = at[k][tr * 8 + r];
                xv[r] = xs[k][tr * 8 + r];
            }
            #pragma unroll
            for (int c = 0; c < 8; c++) {
                w1[c] = Wa[k][c0 + c];
                w2[c] = Wc[k][c0 + c];
            }
            #pragma unroll
            for (int r = 0; r < 8; r++)
                #pragma unroll
                for (int c = 0; c < 8; c++)
                    acc[r][c] += a[r] * w1[c] + xv[r] * w2[c];
        }
    }

    float b[8];
    #pragma unroll
    for (int c = 0; c < 8; c++) {
        int j = c0 + c;
        b[c] = pos_side ? bp[j] : bn[j - 64];
    }
    #pragma unroll
    for (int r = 0; r < 8; r++) {
        int grow = row0 + tr * 8 + r;
        if (grow < N_NODES) {
            #pragma unroll
            for (int c = 0; c < 8; c++)
                out[grow * 128 + c0 + c] = acc[r][c] + b[c];
        }
    }
}

// ---------------------------------------------------------------------------
extern "C" void kernel_launch(void* const* d_in, const int* in_sizes, int n_in,
                              void* d_out, int out_size) {
    const float* x   = (const float*)d_in[0];
    const int*   pe  = (const int*)d_in[1];   // int32 (JAX downcasts int64)
    const int*   ne  = (const int*)d_in[2];
    const float* Wp  = (const float*)d_in[3];
    const float* Wpc = (const float*)d_in[4];
    const float* bp  = (const float*)d_in[5];
    const float* Wn  = (const float*)d_in[6];
    const float* Wnc = (const float*)d_in[7];
    const float* bn  = (const float*)d_in[8];
    float* out = (float*)d_out;

    int E = in_sizes[1] / 2;   // edge_index is [2, E]

    zero_cnt_kernel<<<(TOT_CNT + 255) / 256, 256>>>();
    hist_kernel<<<(2 * E + 255) / 256, 256>>>(pe, ne, E);
    scanA_kernel<<<SCAN_BLOCKS, 256>>>();
    scanB_kernel<<<1, 256>>>();
    scanC_kernel<<<SCAN_BLOCKS, 256>>>();
    fill_kernel<<<(2 * E + 255) / 256, 256>>>(pe, ne, E);
    gather_kernel<<<(2 * N_NODES * 16 + 255) / 256, 256>>>(x);
    gemm_kernel<<<(N_NODES + 127) / 128, 256>>>(x, Wp, Wpc, bp, Wn, Wnc, bn, out);
}

// round 8
// speedup vs baseline: 1.5618x; 1.1017x over previous
#include <cuda_runtime.h>
#include <cuda_bf16.h>
#include <mma.h>

using namespace nvcuda;

// Problem constants (fixed by the dataset)
#define N_NODES 100000
#define F_DIM   64
#define E_MAX   1600000
#define TOT_CNT (2 * N_NODES)            // 200000 flat counters (pos then neg)
#define SCAN_BLOCKS ((TOT_CNT + 1023) / 1024)   // 196

// Scratch (device globals only — no cudaMalloc allowed).
__device__ __align__(16) float g_sum[2][N_NODES * F_DIM];  // mean features
__device__ __align__(16) int g_cnt [TOT_CNT];       // flat histogram
__device__ __align__(16) int g_off [TOT_CNT + 1];   // flat CSR offsets
__device__ __align__(16) int g_cur [TOT_CNT];       // fill cursors
__device__ int g_part [SCAN_BLOCKS];                // per-block partial sums
__device__ int g_bloff[SCAN_BLOCKS];                // per-block exclusive offset
__device__ int g_srcs [2 * E_MAX];                  // dst-sorted src ids (flat)

// ---------------------------------------------------------------------------
// 1) zero histogram counters.
// ---------------------------------------------------------------------------
__global__ void zero_cnt_kernel() {
    unsigned i = blockIdx.x * blockDim.x + threadIdx.x;
    if (i < TOT_CNT) g_cnt[i] = 0;
}

// ---------------------------------------------------------------------------
// 2) histogram of dst (flat: set1 counters live at N_NODES + dst).
// ---------------------------------------------------------------------------
__global__ void hist_kernel(const int* __restrict__ pos_ei,
                            const int* __restrict__ neg_ei, int E) {
    unsigned i = blockIdx.x * blockDim.x + threadIdx.x;
    if (i >= 2u * (unsigned)E) return;
    int set = (i >= (unsigned)E);
    unsigned e = set ? i - (unsigned)E : i;
    const int* ei = set ? neg_ei : pos_ei;
    int dst = ei[(unsigned)E + e];
    atomicAdd(&g_cnt[set * N_NODES + dst], 1);
}

// ---------------------------------------------------------------------------
// 3a) per-block partial sums (1024 counters per block, coalesced int4).
// ---------------------------------------------------------------------------
__global__ void scanA_kernel() {
    const int b = blockIdx.x, t = threadIdx.x;
    int base = b * 1024 + t * 4;
    int4 v = make_int4(0, 0, 0, 0);
    if (base + 3 < TOT_CNT)      v = *(const int4*)&g_cnt[base];
    else if (base < TOT_CNT) {
        v.x = g_cnt[base];
        if (base + 1 < TOT_CNT) v.y = g_cnt[base + 1];
        if (base + 2 < TOT_CNT) v.z = g_cnt[base + 2];
    }
    int s = v.x + v.y + v.z + v.w;
    for (int d = 16; d > 0; d >>= 1) s += __shfl_down_sync(0xffffffffu, s, d);
    __shared__ int ws[8];
    if ((t & 31) == 0) ws[t >> 5] = s;
    __syncthreads();
    if (t == 0) {
        int tot = 0;
        #pragma unroll
        for (int w = 0; w < 8; w++) tot += ws[w];
        g_part[b] = tot;
    }
}

// ---------------------------------------------------------------------------
// 3b) scan of the block partials (single small block).
// ---------------------------------------------------------------------------
__global__ void scanB_kernel() {
    const int t = threadIdx.x;
    __shared__ int sm[256];
    int v = (t < SCAN_BLOCKS) ? g_part[t] : 0;
    sm[t] = v;
    __syncthreads();
    for (int d = 1; d < 256; d <<= 1) {
        int u = (t >= d) ? sm[t - d] : 0;
        __syncthreads();
        sm[t] += u;
        __syncthreads();
    }
    if (t < SCAN_BLOCKS) g_bloff[t] = sm[t] - v;     // exclusive
    if (t == 255) g_off[TOT_CNT] = sm[255];          // grand total
}

// ---------------------------------------------------------------------------
// 3c) write flat exclusive offsets + cursors (coalesced).
// ---------------------------------------------------------------------------
__global__ void scanC_kernel() {
    const int b = blockIdx.x, t = threadIdx.x;
    int base = b * 1024 + t * 4;
    int4 v = make_int4(0, 0, 0, 0);
    if (base + 3 < TOT_CNT)      v = *(const int4*)&g_cnt[base];
    else if (base < TOT_CNT) {
        v.x = g_cnt[base];
        if (base + 1 < TOT_CNT) v.y = g_cnt[base + 1];
        if (base + 2 < TOT_CNT) v.z = g_cnt[base + 2];
    }
    int ts = v.x + v.y + v.z + v.w;
    __shared__ int sm[256];
    sm[t] = ts;
    __syncthreads();
    for (int d = 1; d < 256; d <<= 1) {
        int u = (t >= d) ? sm[t - d] : 0;
        __syncthreads();
        sm[t] += u;
        __syncthreads();
    }
    int o = g_bloff[b] + sm[t] - ts;
    if (base < TOT_CNT) {
        int o0 = o, o1 = o0 + v.x, o2 = o1 + v.y, o3 = o2 + v.z;
        g_off[base] = o0; g_cur[base] = o0;
        if (base + 1 < TOT_CNT) { g_off[base + 1] = o1; g_cur[base + 1] = o1; }
        if (base + 2 < TOT_CNT) { g_off[base + 2] = o2; g_cur[base + 2] = o2; }
        if (base + 3 < TOT_CNT) { g_off[base + 3] = o3; g_cur[base + 3] = o3; }
    }
}

// ---------------------------------------------------------------------------
// 4) fill: counting-sort edges by dst (src ids into flat CSR slots).
// ---------------------------------------------------------------------------
__global__ void fill_kernel(const int* __restrict__ pos_ei,
                            const int* __restrict__ neg_ei, int E) {
    unsigned i = blockIdx.x * blockDim.x + threadIdx.x;
    if (i >= 2u * (unsigned)E) return;
    int set = (i >= (unsigned)E);
    unsigned e = set ? i - (unsigned)E : i;
    const int* ei = set ? neg_ei : pos_ei;
    int src = ei[e];
    int dst = ei[(unsigned)E + e];
    int pos = atomicAdd(&g_cur[set * N_NODES + dst], 1);
    g_srcs[pos] = src;
}

// ---------------------------------------------------------------------------
// 5) gather: per (set,node,chunk) thread, 4-way unrolled register
//    accumulation of the neighborhood; store the MEAN. No atomics.
// ---------------------------------------------------------------------------
__global__ void gather_kernel(const float* __restrict__ x) {
    unsigned idx = blockIdx.x * blockDim.x + threadIdx.x;
    const unsigned per_set = (unsigned)N_NODES * 16u;
    if (idx >= 2u * per_set) return;
    int set = (idx >= per_set);
    unsigned r = set ? idx - per_set : idx;
    unsigned n = r >> 4;
    unsigned c = r & 15u;
    unsigned gid = (unsigned)set * N_NODES + n;

    int beg = g_off[gid];
    int end = g_off[gid + 1];

    float4 a0 = make_float4(0.f,0.f,0.f,0.f), a1 = a0, a2 = a0, a3 = a0;
    int e = beg;
    for (; e + 4 <= end; e += 4) {
        int s0 = __ldg(&g_srcs[e]);
        int s1 = __ldg(&g_srcs[e + 1]);
        int s2 = __ldg(&g_srcs[e + 2]);
        int s3 = __ldg(&g_srcs[e + 3]);
        float4 v0 = __ldg((const float4*)(x + (unsigned)s0 * 64u) + c);
        float4 v1 = __ldg((const float4*)(x + (unsigned)s1 * 64u) + c);
        float4 v2 = __ldg((const float4*)(x + (unsigned)s2 * 64u) + c);
        float4 v3 = __ldg((const float4*)(x + (unsigned)s3 * 64u) + c);
        a0.x += v0.x; a0.y += v0.y; a0.z += v0.z; a0.w += v0.w;
        a1.x += v1.x; a1.y += v1.y; a1.z += v1.z; a1.w += v1.w;
        a2.x += v2.x; a2.y += v2.y; a2.z += v2.z; a2.w += v2.w;
        a3.x += v3.x; a3.y += v3.y; a3.z += v3.z; a3.w += v3.w;
    }
    for (; e < end; e++) {
        int s0 = __ldg(&g_srcs[e]);
        float4 v0 = __ldg((const float4*)(x + (unsigned)s0 * 64u) + c);
        a0.x += v0.x; a0.y += v0.y; a0.z += v0.z; a0.w += v0.w;
    }
    float4 acc;
    acc.x = (a0.x + a1.x) + (a2.x + a3.x);
    acc.y = (a0.y + a1.y) + (a2.y + a3.y);
    acc.z = (a0.z + a1.z) + (a2.z + a3.z);
    acc.w = (a0.w + a1.w) + (a2.w + a3.w);
    float inv = 1.f / (float)max(end - beg, 1);
    acc.x *= inv; acc.y *= inv; acc.z *= inv; acc.w *= inv;
    ((float4*)(g_sum[set] + n * 64u))[c] = acc;
}

// ---------------------------------------------------------------------------
// 6) fused GEMM via tensor cores (3xTF32 split, single accumulator):
//   out[:, side*64 + n0..n0+15] = mean_side @ W1^T + x @ W2^T + b
// Block = 16 node rows x 128 out cols, 8 warps, each warp one 16x16 tile.
// ---------------------------------------------------------------------------
__global__ __launch_bounds__(256) void gemm_kernel(
        const float* __restrict__ x,
        const float* __restrict__ Wp,
        const float* __restrict__ Wpc,
        const float* __restrict__ bp,
        const float* __restrict__ Wn,
        const float* __restrict__ Wnc,
        const float* __restrict__ bn,
        float* __restrict__ out) {
    const int m0   = blockIdx.x * 16;
    const int w    = threadIdx.x >> 5;
    const int lane = threadIdx.x & 31;
    const int side = w >> 2;              // 0 = pos, 1 = neg
    const int n0   = (w & 3) * 16;

    const float* A1 = g_sum[side];                 // mean features
    const float* W1 = side ? Wn  : Wp;
    const float* W2 = side ? Wnc : Wpc;
    const float* bb = side ? bn  : bp;

    wmma::fragment<wmma::accumulator, 16, 16, 8, float> acc;
    wmma::fill_fragment(acc, 0.0f);

    wmma::fragment<wmma::matrix_a, 16, 16, 8, wmma::precision::tf32, wmma::row_major> af, a_hi, a_lo;
    wmma::fragment<wmma::matrix_b, 16, 16, 8, wmma::precision::tf32, wmma::col_major> bf, b_hi, b_lo;

    #pragma unroll
    for (int k = 0; k < 64; k += 8) {
        // ---- term 1: mean @ W1^T ----
        wmma::load_matrix_sync(af, A1 + m0 * 64 + k, 64);
        wmma::load_matrix_sync(bf, W1 + n0 * 64 + k, 64);   // col-major view = W^T
        #pragma unroll
        for (int i = 0; i < af.num_elements; i++) {
            float v  = af.x[i];
            float hi = wmma::__float_to_tf32(v);
            a_hi.x[i] = hi;
            a_lo.x[i] = wmma::__float_to_tf32(v - hi);
        }
        #pragma unroll
        for (int i = 0; i < bf.num_elements; i++) {
            float v  = bf.x[i];
            float hi = wmma::__float_to_tf32(v);
            b_hi.x[i] = hi;
            b_lo.x[i] = wmma::__float_to_tf32(v - hi);
        }
        wmma::mma_sync(acc, a_hi, b_hi, acc);
        wmma::mma_sync(acc, a_hi, b_lo, acc);
        wmma::mma_sync(acc, a_lo, b_hi, acc);

        // ---- term 2: x @ W2^T (same accumulator) ----
        wmma::load_matrix_sync(af, x + m0 * 64 + k, 64);
        wmma::load_matrix_sync(bf, W2 + n0 * 64 + k, 64);
        #pragma unroll
        for (int i = 0; i < af.num_elements; i++) {
            float v  = af.x[i];
            float hi = wmma::__float_to_tf32(v);
            a_hi.x[i] = hi;
            a_lo.x[i] = wmma::__float_to_tf32(v - hi);
        }
        #pragma unroll
        for (int i = 0; i < bf.num_elements; i++) {
            float v  = bf.x[i];
            float hi = wmma::__float_to_tf32(v);
            b_hi.x[i] = hi;
            b_lo.x[i] = wmma::__float_to_tf32(v - hi);
        }
        wmma::mma_sync(acc, a_hi, b_hi, acc);
        wmma::mma_sync(acc, a_hi, b_lo, acc);
        wmma::mma_sync(acc, a_lo, b_hi, acc);
    }

    // Epilogue: bias + store via smem round-trip.
    __shared__ float sm[8][16][16];
    wmma::store_matrix_sync(&sm[w][0][0], acc, 16, wmma::mem_row_major);
    __syncwarp();

    #pragma unroll
    for (int t = 0; t < 8; t++) {
        int elem = lane + t * 32;
        int i = elem >> 4;
        int j = elem & 15;
        float val = sm[w][i][j] + __ldg(&bb[n0 + j]);
        int grow = m0 + i;
        if (grow < N_NODES)
            out[grow * 128 + side * 64 + n0 + j] = val;
    }
}

// ---------------------------------------------------------------------------
extern "C" void kernel_launch(void* const* d_in, const int* in_sizes, int n_in,
                              void* d_out, int out_size) {
    const float* x   = (const float*)d_in[0];
    const int*   pe  = (const int*)d_in[1];   // int32 (JAX downcasts int64)
    const int*   ne  = (const int*)d_in[2];
    const float* Wp  = (const float*)d_in[3];
    const float* Wpc = (const float*)d_in[4];
    const float* bp  = (const float*)d_in[5];
    const float* Wn  = (const float*)d_in[6];
    const float* Wnc = (const float*)d_in[7];
    const float* bn  = (const float*)d_in[8];
    float* out = (float*)d_out;

    int E = in_sizes[1] / 2;   // edge_index is [2, E]

    zero_cnt_kernel<<<(TOT_CNT + 255) / 256, 256>>>();
    hist_kernel<<<(2 * E + 255) / 256, 256>>>(pe, ne, E);
    scanA_kernel<<<SCAN_BLOCKS, 256>>>();
    scanB_kernel<<<1, 256>>>();
    scanC_kernel<<<SCAN_BLOCKS, 256>>>();
    fill_kernel<<<(2 * E + 255) / 256, 256>>>(pe, ne, E);
    gather_kernel<<<(2 * N_NODES * 16 + 255) / 256, 256>>>(x);
    gemm_kernel<<<(N_NODES + 15) / 16, 256>>>(x, Wp, Wpc, bp, Wn, Wnc, bn, out);
}

// round 9
// speedup vs baseline: 1.7544x; 1.1233x over previous
#include <cuda_runtime.h>
#include <cuda_bf16.h>
#include <mma.h>

using namespace nvcuda;

// Problem constants (fixed by the dataset)
#define N_NODES 100000
#define F_DIM   64
#define E_MAX   1600000
#define TOT_CNT (2 * N_NODES)            // 200000 flat counters (pos then neg)
#define SCAN_BLOCKS ((TOT_CNT + 1023) / 1024)   // 196

// Scratch (device globals only — no cudaMalloc allowed).
__device__ __align__(16) float g_sum[2][N_NODES * F_DIM];  // mean features
__device__ __align__(16) int g_cnt [TOT_CNT];       // flat histogram
__device__ __align__(16) int g_off [TOT_CNT + 1];   // flat CSR offsets
__device__ __align__(16) int g_cur [TOT_CNT];       // fill cursors
__device__ int g_part [SCAN_BLOCKS];                // per-block partial sums
__device__ int g_bloff[SCAN_BLOCKS];                // per-block exclusive offset
__device__ int g_srcs [2 * E_MAX];                  // dst-sorted src ids (flat)
__device__ int g_arrive;                            // scan arrival counter
__device__ int g_flag;                              // scan release flag

// ---------------------------------------------------------------------------
// 1) zero histogram counters + scan sync state.
// ---------------------------------------------------------------------------
__global__ void zero_cnt_kernel() {
    unsigned i = blockIdx.x * blockDim.x + threadIdx.x;
    if (i < TOT_CNT) g_cnt[i] = 0;
    if (i == 0) { g_arrive = 0; g_flag = 0; }
}

// ---------------------------------------------------------------------------
// 2) histogram of dst (flat: set1 counters live at N_NODES + dst).
// ---------------------------------------------------------------------------
__global__ void hist_kernel(const int* __restrict__ pos_ei,
                            const int* __restrict__ neg_ei, int E) {
    unsigned i = blockIdx.x * blockDim.x + threadIdx.x;
    if (i >= 2u * (unsigned)E) return;
    int set = (i >= (unsigned)E);
    unsigned e = set ? i - (unsigned)E : i;
    const int* ei = set ? neg_ei : pos_ei;
    int dst = ei[(unsigned)E + e];
    atomicAdd(&g_cnt[set * N_NODES + dst], 1);
}

// ---------------------------------------------------------------------------
// 3) single-pass fused scan (196 blocks, one wave -> spin is safe).
//    Each block: local scan of its 1024 counters, publish partial, last
//    block scans the 196 partials, all blocks then write offsets+cursors.
// ---------------------------------------------------------------------------
__global__ void scan_fused_kernel() {
    const int b = blockIdx.x, t = threadIdx.x;
    int base = b * 1024 + t * 4;
    int4 v = make_int4(0, 0, 0, 0);
    if (base + 3 < TOT_CNT)      v = *(const int4*)&g_cnt[base];
    else if (base < TOT_CNT) {
        v.x = g_cnt[base];
        if (base + 1 < TOT_CNT) v.y = g_cnt[base + 1];
        if (base + 2 < TOT_CNT) v.z = g_cnt[base + 2];
    }
    int ts = v.x + v.y + v.z + v.w;

    __shared__ int sm[256];
    sm[t] = ts;
    __syncthreads();
    for (int d = 1; d < 256; d <<= 1) {
        int u = (t >= d) ? sm[t - d] : 0;
        __syncthreads();
        sm[t] += u;
        __syncthreads();
    }
    int incl = sm[t];                    // inclusive prefix within block

    if (t == 255) g_part[b] = incl;      // block total
    __threadfence();
    __syncthreads();

    if (t == 0) {
        int old = atomicAdd(&g_arrive, 1);
        if (old == SCAN_BLOCKS - 1) {    // last arriving block scans partials
            int run = 0;
            for (int i = 0; i < SCAN_BLOCKS; i++) {
                int p = g_part[i];
                g_bloff[i] = run;
                run += p;
            }
            g_off[TOT_CNT] = run;
            __threadfence();
            atomicExch(&g_flag, 1);
        }
        while (atomicAdd(&g_flag, 0) == 0) __nanosleep(200);
    }
    __syncthreads();

    int o = g_bloff[b] + incl - ts;      // global exclusive prefix
    if (base < TOT_CNT) {
        int o0 = o, o1 = o0 + v.x, o2 = o1 + v.y, o3 = o2 + v.z;
        g_off[base] = o0; g_cur[base] = o0;
        if (base + 1 < TOT_CNT) { g_off[base + 1] = o1; g_cur[base + 1] = o1; }
        if (base + 2 < TOT_CNT) { g_off[base + 2] = o2; g_cur[base + 2] = o2; }
        if (base + 3 < TOT_CNT) { g_off[base + 3] = o3; g_cur[base + 3] = o3; }
    }
}

// ---------------------------------------------------------------------------
// 4) fill: counting-sort edges by dst (src ids into flat CSR slots).
// ---------------------------------------------------------------------------
__global__ void fill_kernel(const int* __restrict__ pos_ei,
                            const int* __restrict__ neg_ei, int E) {
    unsigned i = blockIdx.x * blockDim.x + threadIdx.x;
    if (i >= 2u * (unsigned)E) return;
    int set = (i >= (unsigned)E);
    unsigned e = set ? i - (unsigned)E : i;
    const int* ei = set ? neg_ei : pos_ei;
    int src = ei[e];
    int dst = ei[(unsigned)E + e];
    int pos = atomicAdd(&g_cur[set * N_NODES + dst], 1);
    g_srcs[pos] = src;
}

// ---------------------------------------------------------------------------
// 5) gather: 16 threads per (set,node); preload 8 indices then 8 independent
//    float4 loads per iteration (deep MLP). Store the MEAN. No atomics.
// ---------------------------------------------------------------------------
__global__ void gather_kernel(const float* __restrict__ x) {
    unsigned idx = blockIdx.x * blockDim.x + threadIdx.x;
    const unsigned per_set = (unsigned)N_NODES * 16u;
    if (idx >= 2u * per_set) return;
    int set = (idx >= per_set);
    unsigned r = set ? idx - per_set : idx;
    unsigned n = r >> 4;
    unsigned c = r & 15u;
    unsigned gid = (unsigned)set * N_NODES + n;

    int beg = g_off[gid];
    int end = g_off[gid + 1];

    float4 a0 = make_float4(0.f,0.f,0.f,0.f), a1 = a0, a2 = a0, a3 = a0;
    int e = beg;
    for (; e + 8 <= end; e += 8) {
        int s[8];
        #pragma unroll
        for (int j = 0; j < 8; j++) s[j] = __ldg(&g_srcs[e + j]);
        float4 v[8];
        #pragma unroll
        for (int j = 0; j < 8; j++)
            v[j] = __ldg((const float4*)(x + (unsigned)s[j] * 64u) + c);
        a0.x += v[0].x + v[4].x; a0.y += v[0].y + v[4].y;
        a0.z += v[0].z + v[4].z; a0.w += v[0].w + v[4].w;
        a1.x += v[1].x + v[5].x; a1.y += v[1].y + v[5].y;
        a1.z += v[1].z + v[5].z; a1.w += v[1].w + v[5].w;
        a2.x += v[2].x + v[6].x; a2.y += v[2].y + v[6].y;
        a2.z += v[2].z + v[6].z; a2.w += v[2].w + v[6].w;
        a3.x += v[3].x + v[7].x; a3.y += v[3].y + v[7].y;
        a3.z += v[3].z + v[7].z; a3.w += v[3].w + v[7].w;
    }
    if (e + 4 <= end) {
        int s[4];
        #pragma unroll
        for (int j = 0; j < 4; j++) s[j] = __ldg(&g_srcs[e + j]);
        float4 v[4];
        #pragma unroll
        for (int j = 0; j < 4; j++)
            v[j] = __ldg((const float4*)(x + (unsigned)s[j] * 64u) + c);
        a0.x += v[0].x; a0.y += v[0].y; a0.z += v[0].z; a0.w += v[0].w;
        a1.x += v[1].x; a1.y += v[1].y; a1.z += v[1].z; a1.w += v[1].w;
        a2.x += v[2].x; a2.y += v[2].y; a2.z += v[2].z; a2.w += v[2].w;
        a3.x += v[3].x; a3.y += v[3].y; a3.z += v[3].z; a3.w += v[3].w;
        e += 4;
    }
    for (; e < end; e++) {
        int s0 = __ldg(&g_srcs[e]);
        float4 v0 = __ldg((const float4*)(x + (unsigned)s0 * 64u) + c);
        a0.x += v0.x; a0.y += v0.y; a0.z += v0.z; a0.w += v0.w;
    }
    float4 acc;
    acc.x = (a0.x + a1.x) + (a2.x + a3.x);
    acc.y = (a0.y + a1.y) + (a2.y + a3.y);
    acc.z = (a0.z + a1.z) + (a2.z + a3.z);
    acc.w = (a0.w + a1.w) + (a2.w + a3.w);
    float inv = 1.f / (float)max(end - beg, 1);
    acc.x *= inv; acc.y *= inv; acc.z *= inv; acc.w *= inv;
    ((float4*)(g_sum[set] + n * 64u))[c] = acc;
}

// ---------------------------------------------------------------------------
// 6) fused GEMM via tensor cores (3xTF32), A tiles staged in smem once per
//    block and shared by all 8 warps. 16 rows x 128 cols per block.
//    N_NODES % 16 == 0 -> no bounds checks.
// ---------------------------------------------------------------------------
__global__ __launch_bounds__(256) void gemm_kernel(
        const float* __restrict__ x,
        const float* __restrict__ Wp,
        const float* __restrict__ Wpc,
        const float* __restrict__ bp,
        const float* __restrict__ Wn,
        const float* __restrict__ Wnc,
        const float* __restrict__ bn,
        float* __restrict__ out) {
    __shared__ float sx [16][68];
    __shared__ float ssp[16][68];
    __shared__ float ssn[16][68];
    __shared__ float smo[8][16][16];

    const int tid  = threadIdx.x;
    const int m0   = blockIdx.x * 16;
    const int w    = tid >> 5;
    const int lane = tid & 31;
    const int side = w >> 2;              // 0 = pos, 1 = neg
    const int n0   = (w & 3) * 16;

    // ---- stage A tiles: each thread one float4 per array ----
    {
        int r  = tid >> 4;                // row 0..15
        int ch = tid & 15;                // float4 chunk 0..15
        int grow = m0 + r;
        float4 vx = *((const float4*)(x        + grow * 64) + ch);
        float4 vp = *((const float4*)(g_sum[0] + grow * 64) + ch);
        float4 vn = *((const float4*)(g_sum[1] + grow * 64) + ch);
        int cc = ch * 4;
        sx [r][cc+0] = vx.x; sx [r][cc+1] = vx.y; sx [r][cc+2] = vx.z; sx [r][cc+3] = vx.w;
        ssp[r][cc+0] = vp.x; ssp[r][cc+1] = vp.y; ssp[r][cc+2] = vp.z; ssp[r][cc+3] = vp.w;
        ssn[r][cc+0] = vn.x; ssn[r][cc+1] = vn.y; ssn[r][cc+2] = vn.z; ssn[r][cc+3] = vn.w;
    }
    __syncthreads();

    const float* A1 = side ? &ssn[0][0] : &ssp[0][0];
    const float* W1 = side ? Wn  : Wp;
    const float* W2 = side ? Wnc : Wpc;
    const float* bb = side ? bn  : bp;

    wmma::fragment<wmma::accumulator, 16, 16, 8, float> acc;
    wmma::fill_fragment(acc, 0.0f);

    wmma::fragment<wmma::matrix_a, 16, 16, 8, wmma::precision::tf32, wmma::row_major> af, a_hi, a_lo;
    wmma::fragment<wmma::matrix_b, 16, 16, 8, wmma::precision::tf32, wmma::col_major> bf, b_hi, b_lo;

    #pragma unroll
    for (int k = 0; k < 64; k += 8) {
        // ---- term 1: mean @ W1^T ----
        wmma::load_matrix_sync(af, A1 + k, 68);
        wmma::load_matrix_sync(bf, W1 + n0 * 64 + k, 64);   // col-major = W^T
        #pragma unroll
        for (int i = 0; i < af.num_elements; i++) {
            float v  = af.x[i];
            float hi = wmma::__float_to_tf32(v);
            a_hi.x[i] = hi;
            a_lo.x[i] = wmma::__float_to_tf32(v - hi);
        }
        #pragma unroll
        for (int i = 0; i < bf.num_elements; i++) {
            float v  = bf.x[i];
            float hi = wmma::__float_to_tf32(v);
            b_hi.x[i] = hi;
            b_lo.x[i] = wmma::__float_to_tf32(v - hi);
        }
        wmma::mma_sync(acc, a_hi, b_hi, acc);
        wmma::mma_sync(acc, a_hi, b_lo, acc);
        wmma::mma_sync(acc, a_lo, b_hi, acc);

        // ---- term 2: x @ W2^T (same accumulator) ----
        wmma::load_matrix_sync(af, &sx[0][0] + k, 68);
        wmma::load_matrix_sync(bf, W2 + n0 * 64 + k, 64);
        #pragma unroll
        for (int i = 0; i < af.num_elements; i++) {
            float v  = af.x[i];
            float hi = wmma::__float_to_tf32(v);
            a_hi.x[i] = hi;
            a_lo.x[i] = wmma::__float_to_tf32(v - hi);
        }
        #pragma unroll
        for (int i = 0; i < bf.num_elements; i++) {
            float v  = bf.x[i];
            float hi = wmma::__float_to_tf32(v);
            b_hi.x[i] = hi;
            b_lo.x[i] = wmma::__float_to_tf32(v - hi);
        }
        wmma::mma_sync(acc, a_hi, b_hi, acc);
        wmma::mma_sync(acc, a_hi, b_lo, acc);
        wmma::mma_sync(acc, a_lo, b_hi, acc);
    }

    // Epilogue: bias + store via smem round-trip.
    wmma::store_matrix_sync(&smo[w][0][0], acc, 16, wmma::mem_row_major);
    __syncwarp();

    #pragma unroll
    for (int t = 0; t < 8; t++) {
        int elem = lane + t * 32;
        int i = elem >> 4;
        int j = elem & 15;
        float val = smo[w][i][j] + __ldg(&bb[n0 + j]);
        out[(m0 + i) * 128 + side * 64 + n0 + j] = val;
    }
}

// ---------------------------------------------------------------------------
extern "C" void kernel_launch(void* const* d_in, const int* in_sizes, int n_in,
                              void* d_out, int out_size) {
    const float* x   = (const float*)d_in[0];
    const int*   pe  = (const int*)d_in[1];   // int32 (JAX downcasts int64)
    const int*   ne  = (const int*)d_in[2];
    const float* Wp  = (const float*)d_in[3];
    const float* Wpc = (const float*)d_in[4];
    const float* bp  = (const float*)d_in[5];
    const float* Wn  = (const float*)d_in[6];
    const float* Wnc = (const float*)d_in[7];
    const float* bn  = (const float*)d_in[8];
    float* out = (float*)d_out;

    int E = in_sizes[1] / 2;   // edge_index is [2, E]

    zero_cnt_kernel<<<(TOT_CNT + 255) / 256, 256>>>();
    hist_kernel<<<(2 * E + 255) / 256, 256>>>(pe, ne, E);
    scan_fused_kernel<<<SCAN_BLOCKS, 256>>>();
    fill_kernel<<<(2 * E + 255) / 256, 256>>>(pe, ne, E);
    gather_kernel<<<(2 * N_NODES * 16 + 255) / 256, 256>>>(x);
    gemm_kernel<<<N_NODES / 16, 256>>>(x, Wp, Wpc, bp, Wn, Wnc, bn, out);
}